// round 5
// baseline (speedup 1.0000x reference)
#include <cuda_runtime.h>
#include <cuda_bf16.h>
#include <math.h>
#include <stdint.h>

// Shapes
#define NB   64
#define T1   33
#define TL   32
#define I1   197
#define IP   224      // padded i (multiple of 56-wide warp tiles)
#define CD   512
#define TEMP 0.07f
#define NCH  8        // K chunks of 64
#define A_CH 16384    // A chunk image: 128 rows x 128B
#define B_CH 28672    // B chunk image: 224 rows x 128B

// Scratch: pre-swizzled, chunk-major SMEM images
__device__ __align__(256) __nv_bfloat16 g_Asw[16 * NCH * A_CH / 2];
__device__ __align__(256) __nv_bfloat16 g_Bsw[NB * NCH * B_CH / 2];
__device__ float g_tti[NB * NB];
__device__ int   g_cnt;

// ---------------------------------------------------------------------------
// Portable PTX helpers
// ---------------------------------------------------------------------------
__device__ __forceinline__ uint32_t smem_u32(const void* p) {
    uint32_t a;
    asm("{ .reg .u64 t; cvta.to.shared.u64 t, %1; cvt.u32.u64 %0, t; }"
        : "=r"(a) : "l"(p));
    return a;
}
#define SWZ(o) ((o) ^ ((((uint32_t)(o)) >> 3) & 0x70u))

__device__ __forceinline__ void bulk_ld(uint32_t dst, const void* src,
                                        uint32_t bytes, uint32_t mbar) {
    asm volatile(
        "cp.async.bulk.shared::cluster.global.mbarrier::complete_tx::bytes "
        "[%0], [%1], %2, [%3];"
        :: "r"(dst), "l"(src), "r"(bytes), "r"(mbar) : "memory");
}
__device__ __forceinline__ void mbar_init(uint32_t m, uint32_t cnt) {
    asm volatile("mbarrier.init.shared.b64 [%0], %1;" :: "r"(m), "r"(cnt) : "memory");
}
__device__ __forceinline__ void mbar_expect(uint32_t m, uint32_t bytes) {
    asm volatile("mbarrier.arrive.expect_tx.shared.b64 _, [%0], %1;"
                 :: "r"(m), "r"(bytes) : "memory");
}
__device__ __forceinline__ void mbar_arrive(uint32_t m) {
    asm volatile("mbarrier.arrive.shared.b64 _, [%0];" :: "r"(m) : "memory");
}
#define MBAR_WAIT(addr, par) do {                                               \
    uint32_t _m = (addr), _p = (par), _d;                                       \
    asm volatile("{\n\t.reg .pred p;\n\t"                                       \
        "mbarrier.try_wait.parity.acquire.cta.shared::cta.b64 p, [%1], %2;\n\t" \
        "selp.b32 %0, 1, 0, p;\n\t}" : "=r"(_d) : "r"(_m), "r"(_p) : "memory"); \
    if (!_d) {                                                                  \
        asm volatile("{\n\t.reg .pred P1;\n\tWL_%=:\n\t"                        \
            "mbarrier.try_wait.parity.acquire.cta.shared::cta.b64 P1, [%0], %1, 0x989680;\n\t" \
            "@P1 bra.uni WD_%=;\n\tbra.uni WL_%=;\n\tWD_%=:\n\t}"               \
            :: "r"(_m), "r"(_p) : "memory");                                    \
    }                                                                           \
} while (0)

__device__ __forceinline__ void ldm_x4(uint32_t& r0, uint32_t& r1,
                                       uint32_t& r2, uint32_t& r3, uint32_t a) {
    asm volatile("ldmatrix.sync.aligned.m8n8.x4.shared.b16 {%0,%1,%2,%3}, [%4];"
                 : "=r"(r0), "=r"(r1), "=r"(r2), "=r"(r3) : "r"(a));
}
__device__ __forceinline__ void ldm_x2(uint32_t& r0, uint32_t& r1, uint32_t a) {
    asm volatile("ldmatrix.sync.aligned.m8n8.x2.shared.b16 {%0,%1}, [%2];"
                 : "=r"(r0), "=r"(r1) : "r"(a));
}
__device__ __forceinline__ void mma16816(float* d, const uint32_t* a,
                                         uint32_t b0, uint32_t b1) {
    asm volatile(
        "mma.sync.aligned.m16n8k16.row.col.f32.bf16.bf16.f32 "
        "{%0,%1,%2,%3}, {%4,%5,%6,%7}, {%8,%9}, {%0,%1,%2,%3};"
        : "+f"(d[0]), "+f"(d[1]), "+f"(d[2]), "+f"(d[3])
        : "r"(a[0]), "r"(a[1]), "r"(a[2]), "r"(a[3]), "r"(b0), "r"(b1));
}

// ---------------------------------------------------------------------------
// knorm: grid (64,2), block 512. by==0 -> text, by==1 -> video.
// Writes bf16 directly in swizzled chunk-major SMEM image.
// ---------------------------------------------------------------------------
__global__ void knorm(const float* __restrict__ text, const float* __restrict__ video) {
    int b = blockIdx.x, d = threadIdx.x;
    if (blockIdx.y == 0) {
        if (b == 0 && d == 0) g_cnt = 0;
        const float* p = text + (size_t)b * T1 * CD + d;
        float s = 0.f;
#pragma unroll
        for (int t = 0; t < T1; t++) { float v = p[t * CD]; s += v * v; }
        float inv = 1.0f / sqrtf(s);
        char* base = (char*)g_Asw + (((size_t)(b >> 2)) * NCH + (d >> 6)) * A_CH;
        uint32_t colb = (d & 63) * 2;
#pragma unroll 4
        for (int t = 0; t < TL; t++) {
            int row = (b & 3) * 32 + t;
            *(__nv_bfloat16*)(base + SWZ(row * 128 + colb)) =
                __float2bfloat16(p[(t + 1) * CD] * inv);
        }
    } else {
        const float* p = video + (size_t)b * I1 * CD + d;
        float s = 0.f;
#pragma unroll 4
        for (int t = 0; t < I1; t++) { float v = p[t * CD]; s += v * v; }
        float inv = 1.0f / sqrtf(s);
        char* base = (char*)g_Bsw + ((size_t)b * NCH + (d >> 6)) * B_CH;
        uint32_t colb = (d & 63) * 2;
        for (int t = 0; t < I1; t++)
            *(__nv_bfloat16*)(base + SWZ(t * 128 + colb)) =
                __float2bfloat16(p[t * CD] * inv);
        __nv_bfloat16 z = __float2bfloat16(0.f);
        for (int t = I1; t < IP; t++)
            *(__nv_bfloat16*)(base + SWZ(t * 128 + colb)) = z;
    }
}

// ---------------------------------------------------------------------------
// ksim: CTA (q,y): D[128,224] = A(128x512)*B(224x512)^T. 16 warps 4(M)x4(N),
// warp tile 32x56. 4-stage bulk ring; full[s]=tx mbar, empty[s]=16-arrive mbar;
// NO __syncthreads in the mainloop. Fused max/mean epilogue + last-CTA loss.
// ---------------------------------------------------------------------------
#define SM_RMAX  0
#define SM_MBF   2048        // full barriers (4 x 8B)
#define SM_MBE   2112        // empty barriers (4 x 8B)
#define SM_STG   4096
#define STG_SZ   (A_CH + B_CH)              // 45056
#define SM_TOTAL (SM_STG + 4 * STG_SZ)      // 184320

__global__ void __launch_bounds__(512, 1)
ksim(const int* __restrict__ amask, float* __restrict__ out) {
    extern __shared__ char smem[];
    __shared__ int lastflag;
    const uint32_t sb = smem_u32(smem);
    const int tid = threadIdx.x, wid = tid >> 5, lid = tid & 31;
    const int wm = wid & 3, wn = wid >> 2;
    const int q = blockIdx.x, y = blockIdx.y;

    const char* Asrc = (const char*)g_Asw + (size_t)q * NCH * A_CH;
    const char* Bsrc = (const char*)g_Bsw + (size_t)y * NCH * B_CH;

    if (tid == 0) {
#pragma unroll
        for (int s = 0; s < 4; s++) {
            mbar_init(sb + SM_MBF + 8 * s, 1);
            mbar_init(sb + SM_MBE + 8 * s, 16);
        }
    }
    __syncthreads();
    if (tid == 0) {
#pragma unroll
        for (int s = 0; s < 4; s++) {                 // prologue: chunks 0..3
            uint32_t mb = sb + SM_MBF + 8 * s;
            uint32_t st = sb + SM_STG + s * STG_SZ;
            mbar_expect(mb, STG_SZ);
            bulk_ld(st,        Asrc + (size_t)s * A_CH, A_CH, mb);
            bulk_ld(st + A_CH, Bsrc + (size_t)s * B_CH, B_CH, mb);
        }
    }

    float acc[2][7][4];
#pragma unroll
    for (int mi = 0; mi < 2; mi++)
#pragma unroll
        for (int nj = 0; nj < 7; nj++)
#pragma unroll
            for (int d = 0; d < 4; d++) acc[mi][nj][d] = 0.f;

    // ldmatrix address components (warp-invariant pieces precomputed)
    const int arow = 32 * wm + (lid & 15);
    const int brow = 56 * wn + (lid & 15);
    const int btr  = 56 * wn + 48 + (lid & 7);
    const int chi  = (lid >> 4) * 16;                  // col-half for x4
    const int cht  = ((lid >> 3) & 1) * 16;            // col-half for x2

#pragma unroll 1
    for (int c = 0; c < NCH; c++) {
        const int s = c & 3;
        MBAR_WAIT(sb + SM_MBF + 8 * s, (c >> 2) & 1);
        const uint32_t Abase = sb + SM_STG + s * STG_SZ;
        const uint32_t Bbase = Abase + A_CH;

#pragma unroll
        for (int ks = 0; ks < 4; ks++) {
            const int kb = ks * 32;
            uint32_t af[2][4];
#pragma unroll
            for (int mi = 0; mi < 2; mi++)
                ldm_x4(af[mi][0], af[mi][1], af[mi][2], af[mi][3],
                       Abase + SWZ((arow + 16 * mi) * 128 + kb + chi));
            uint32_t bf[3][4], bt[2];
#pragma unroll
            for (int ni = 0; ni < 3; ni++)
                ldm_x4(bf[ni][0], bf[ni][1], bf[ni][2], bf[ni][3],
                       Bbase + SWZ((brow + 16 * ni) * 128 + kb + chi));
            ldm_x2(bt[0], bt[1], Bbase + SWZ(btr * 128 + kb + cht));
#pragma unroll
            for (int mi = 0; mi < 2; mi++) {
#pragma unroll
                for (int ni = 0; ni < 3; ni++) {
                    mma16816(acc[mi][2 * ni],     af[mi], bf[ni][0], bf[ni][2]);
                    mma16816(acc[mi][2 * ni + 1], af[mi], bf[ni][1], bf[ni][3]);
                }
                mma16816(acc[mi][6], af[mi], bt[0], bt[1]);
            }
        }
        if (lid == 0) mbar_arrive(sb + SM_MBE + 8 * s);   // warp done reading stage s

        if (tid == 0 && c < 4) {                          // refill stage s with chunk c+4
            MBAR_WAIT(sb + SM_MBE + 8 * s, 0);
            uint32_t mb = sb + SM_MBF + 8 * s;
            uint32_t st = Abase;
            mbar_expect(mb, STG_SZ);
            bulk_ld(st,        Asrc + (size_t)(c + 4) * A_CH, A_CH, mb);
            bulk_ld(st + A_CH, Bsrc + (size_t)(c + 4) * B_CH, B_CH, mb);
        }
    }

    // ---- Epilogue: per-row max over i (mask i>=197) -> masked mean over t
    float* rowmax = (float*)(smem + SM_RMAX);          // [128][4]
#pragma unroll
    for (int mi = 0; mi < 2; mi++)
#pragma unroll
        for (int h = 0; h < 2; h++) {
            float m = -3.4e38f;
#pragma unroll
            for (int nj = 0; nj < 7; nj++)
#pragma unroll
                for (int e = 0; e < 2; e++) {
                    int col = 56 * wn + 8 * nj + 2 * (lid & 3) + e;
                    float v = acc[mi][nj][2 * h + e];
                    if (col < I1) m = fmaxf(m, v);
                }
            m = fmaxf(m, __shfl_xor_sync(0xffffffffu, m, 1));
            m = fmaxf(m, __shfl_xor_sync(0xffffffffu, m, 2));
            if ((lid & 3) == 0) {
                int row = 32 * wm + 16 * mi + 8 * h + (lid >> 2);
                rowmax[4 * row + wn] = m;
            }
        }
    __syncthreads();

    if (tid < 128) {
        int row = tid;
        float m = fmaxf(fmaxf(rowmax[4 * row], rowmax[4 * row + 1]),
                        fmaxf(rowmax[4 * row + 2], rowmax[4 * row + 3]));
        int xl = row >> 5, t = row & 31;
        int x = 4 * q + xl;
        int mk = amask[x * T1 + 1 + t] != 0;
        float v = mk ? m * TEMP : 0.f;
        float cnt = mk ? 1.f : 0.f;
#pragma unroll
        for (int o = 16; o > 0; o >>= 1) {
            v   += __shfl_xor_sync(0xffffffffu, v, o);
            cnt += __shfl_xor_sync(0xffffffffu, cnt, o);
        }
        if (t == 0) g_tti[x * NB + y] = v / fmaxf(cnt, 1e-6f);
    }
    __syncthreads();

    // ---- Last CTA computes the loss (threadFenceReduction pattern)
    if (tid == 0) {
        __threadfence();
        lastflag = (atomicAdd(&g_cnt, 1) == 16 * NB - 1);
    }
    __syncthreads();
    if (lastflag) {
        __threadfence();
        float* sl = (float*)(smem + SM_RMAX);          // reuse, [64]
#pragma unroll 1
        for (int rep = 0; rep < 4; rep++) {            // warp wid: rows 4*wid..+3
            int x = 4 * wid + rep;
            const float* row = g_tti + x * NB;
            float e = expf(row[lid]) + expf(row[lid + 32]);
#pragma unroll
            for (int o = 16; o > 0; o >>= 1) e += __shfl_xor_sync(0xffffffffu, e, o);
            if (lid == 0) sl[x] = -logf(expf(row[x]) / e + 1e-20f);
        }
        __syncthreads();
        if (tid < 32) {
            float s = sl[lid] + sl[lid + 32];
#pragma unroll
            for (int o = 16; o > 0; o >>= 1) s += __shfl_xor_sync(0xffffffffu, s, o);
            if (lid == 0) out[0] = s * (1.0f / NB);
        }
    }
}

// ---------------------------------------------------------------------------
extern "C" void kernel_launch(void* const* d_in, const int* in_sizes, int n_in,
                              void* d_out, int out_size) {
    const float* text  = (const float*)d_in[0];
    const float* video = (const float*)d_in[1];
    const int*   mask  = (const int*)d_in[2];

    static int smem_set = 0;
    if (!smem_set) {
        cudaFuncSetAttribute(ksim, cudaFuncAttributeMaxDynamicSharedMemorySize, SM_TOTAL);
        smem_set = 1;
    }

    knorm<<<dim3(NB, 2), 512>>>(text, video);
    ksim<<<dim3(16, NB), 512, SM_TOTAL>>>(mask, (float*)d_out);
}

// round 6
// speedup vs baseline: 1.0935x; 1.0935x over previous
#include <cuda_runtime.h>
#include <cuda_bf16.h>
#include <math.h>
#include <stdint.h>

// Shapes
#define NB   64
#define T1   33
#define TL   32
#define I1   197
#define IP   224      // padded i
#define CD   512
#define TEMP 0.07f
#define NCH  8        // K chunks of 64
#define A_CH 8192     // A chunk image: 64 rows x 128B (per qh)
#define B_CH 28672    // B chunk image: 224 rows x 128B
#define NCTA 2048     // 32 x 64

// Scratch: pre-swizzled, chunk-major SMEM images
__device__ __align__(256) __nv_bfloat16 g_Asw[32 * NCH * A_CH / 2];
__device__ __align__(256) __nv_bfloat16 g_Bsw[NB * NCH * B_CH / 2];
__device__ float g_tti[NB * NB];
__device__ int   g_cnt;

// ---------------------------------------------------------------------------
// Portable PTX helpers
// ---------------------------------------------------------------------------
__device__ __forceinline__ uint32_t smem_u32(const void* p) {
    uint32_t a;
    asm("{ .reg .u64 t; cvta.to.shared.u64 t, %1; cvt.u32.u64 %0, t; }"
        : "=r"(a) : "l"(p));
    return a;
}
#define SWZ(o) ((o) ^ ((((uint32_t)(o)) >> 3) & 0x70u))

__device__ __forceinline__ void bulk_ld(uint32_t dst, const void* src,
                                        uint32_t bytes, uint32_t mbar) {
    asm volatile(
        "cp.async.bulk.shared::cluster.global.mbarrier::complete_tx::bytes "
        "[%0], [%1], %2, [%3];"
        :: "r"(dst), "l"(src), "r"(bytes), "r"(mbar) : "memory");
}
__device__ __forceinline__ void mbar_init(uint32_t m, uint32_t cnt) {
    asm volatile("mbarrier.init.shared.b64 [%0], %1;" :: "r"(m), "r"(cnt) : "memory");
}
__device__ __forceinline__ void mbar_expect(uint32_t m, uint32_t bytes) {
    asm volatile("mbarrier.arrive.expect_tx.shared.b64 _, [%0], %1;"
                 :: "r"(m), "r"(bytes) : "memory");
}
__device__ __forceinline__ void mbar_arrive(uint32_t m) {
    asm volatile("mbarrier.arrive.shared.b64 _, [%0];" :: "r"(m) : "memory");
}
#define MBAR_WAIT(addr, par) do {                                               \
    uint32_t _m = (addr), _p = (par), _d;                                       \
    asm volatile("{\n\t.reg .pred p;\n\t"                                       \
        "mbarrier.try_wait.parity.acquire.cta.shared::cta.b64 p, [%1], %2;\n\t" \
        "selp.b32 %0, 1, 0, p;\n\t}" : "=r"(_d) : "r"(_m), "r"(_p) : "memory"); \
    if (!_d) {                                                                  \
        asm volatile("{\n\t.reg .pred P1;\n\tWL_%=:\n\t"                        \
            "mbarrier.try_wait.parity.acquire.cta.shared::cta.b64 P1, [%0], %1, 0x989680;\n\t" \
            "@P1 bra.uni WD_%=;\n\tbra.uni WL_%=;\n\tWD_%=:\n\t}"               \
            :: "r"(_m), "r"(_p) : "memory");                                    \
    }                                                                           \
} while (0)

__device__ __forceinline__ void ldm_x4(uint32_t& r0, uint32_t& r1,
                                       uint32_t& r2, uint32_t& r3, uint32_t a) {
    asm volatile("ldmatrix.sync.aligned.m8n8.x4.shared.b16 {%0,%1,%2,%3}, [%4];"
                 : "=r"(r0), "=r"(r1), "=r"(r2), "=r"(r3) : "r"(a));
}
__device__ __forceinline__ void ldm_x2(uint32_t& r0, uint32_t& r1, uint32_t a) {
    asm volatile("ldmatrix.sync.aligned.m8n8.x2.shared.b16 {%0,%1}, [%2];"
                 : "=r"(r0), "=r"(r1) : "r"(a));
}
__device__ __forceinline__ void mma16816(float* d, const uint32_t* a,
                                         uint32_t b0, uint32_t b1) {
    asm volatile(
        "mma.sync.aligned.m16n8k16.row.col.f32.bf16.bf16.f32 "
        "{%0,%1,%2,%3}, {%4,%5,%6,%7}, {%8,%9}, {%0,%1,%2,%3};"
        : "+f"(d[0]), "+f"(d[1]), "+f"(d[2]), "+f"(d[3])
        : "r"(a[0]), "r"(a[1]), "r"(a[2]), "r"(a[3]), "r"(b0), "r"(b1));
}

// ---------------------------------------------------------------------------
// knorm: grid (64,2), block 512. by==0 -> text, by==1 -> video.
// ---------------------------------------------------------------------------
__global__ void knorm(const float* __restrict__ text, const float* __restrict__ video) {
    int b = blockIdx.x, d = threadIdx.x;
    if (blockIdx.y == 0) {
        if (b == 0 && d == 0) g_cnt = 0;
        const float* p = text + (size_t)b * T1 * CD + d;
        float s = 0.f;
#pragma unroll
        for (int t = 0; t < T1; t++) { float v = p[t * CD]; s += v * v; }
        float inv = 1.0f / sqrtf(s);
        char* base = (char*)g_Asw + (((size_t)(b >> 1)) * NCH + (d >> 6)) * A_CH;
        uint32_t colb = (d & 63) * 2;
#pragma unroll 4
        for (int t = 0; t < TL; t++) {
            int row = (b & 1) * 32 + t;
            *(__nv_bfloat16*)(base + SWZ(row * 128 + colb)) =
                __float2bfloat16(p[(t + 1) * CD] * inv);
        }
    } else {
        const float* p = video + (size_t)b * I1 * CD + d;
        float s = 0.f;
#pragma unroll 4
        for (int t = 0; t < I1; t++) { float v = p[t * CD]; s += v * v; }
        float inv = 1.0f / sqrtf(s);
        char* base = (char*)g_Bsw + ((size_t)b * NCH + (d >> 6)) * B_CH;
        uint32_t colb = (d & 63) * 2;
        for (int t = 0; t < I1; t++)
            *(__nv_bfloat16*)(base + SWZ(t * 128 + colb)) =
                __float2bfloat16(p[t * CD] * inv);
        __nv_bfloat16 z = __float2bfloat16(0.f);
        for (int t = I1; t < IP; t++)
            *(__nv_bfloat16*)(base + SWZ(t * 128 + colb)) = z;
    }
}

// ---------------------------------------------------------------------------
// ksim: CTA (qh,y): D[64,224] = A(64x512)*B(224x512)^T. 8 warps 2(M)x4(N),
// warp tile 32x56. 3-stage bulk ring, occupancy 2 per SM.
// ---------------------------------------------------------------------------
#define SM_RMAX  0           // 64*4*4 = 1024B
#define SM_MBF   1024        // full barriers (3 x 8B)
#define SM_MBE   1088        // empty barriers (3 x 8B)
#define SM_STG   2048
#define STG_SZ   (A_CH + B_CH)              // 36864
#define SM_TOTAL (SM_STG + 3 * STG_SZ)      // 112640

__global__ void __launch_bounds__(256, 2)
ksim(const int* __restrict__ amask, float* __restrict__ out) {
    extern __shared__ char smem[];
    __shared__ int lastflag;
    const uint32_t sb = smem_u32(smem);
    const int tid = threadIdx.x, wid = tid >> 5, lid = tid & 31;
    const int wm = wid & 1, wn = wid >> 1;
    const int qh = blockIdx.x, y = blockIdx.y;

    const char* Asrc = (const char*)g_Asw + (size_t)qh * NCH * A_CH;
    const char* Bsrc = (const char*)g_Bsw + (size_t)y * NCH * B_CH;

    if (tid == 0) {
#pragma unroll
        for (int s = 0; s < 3; s++) {
            mbar_init(sb + SM_MBF + 8 * s, 1);
            mbar_init(sb + SM_MBE + 8 * s, 8);
        }
    }
    __syncthreads();
    if (tid == 0) {
#pragma unroll
        for (int s = 0; s < 3; s++) {                 // prologue: chunks 0..2
            uint32_t mb = sb + SM_MBF + 8 * s;
            uint32_t st = sb + SM_STG + s * STG_SZ;
            mbar_expect(mb, STG_SZ);
            bulk_ld(st,        Asrc + (size_t)s * A_CH, A_CH, mb);
            bulk_ld(st + A_CH, Bsrc + (size_t)s * B_CH, B_CH, mb);
        }
    }

    float acc[2][7][4];
#pragma unroll
    for (int mi = 0; mi < 2; mi++)
#pragma unroll
        for (int nj = 0; nj < 7; nj++)
#pragma unroll
            for (int d = 0; d < 4; d++) acc[mi][nj][d] = 0.f;

    const int arow = 32 * wm + (lid & 15);
    const int brow = 56 * wn + (lid & 15);
    const int btr  = 56 * wn + 48 + (lid & 7);
    const int chi  = (lid >> 4) * 16;
    const int cht  = ((lid >> 3) & 1) * 16;

    int cs = 0;              // stage
    uint32_t ph = 0, eph = 0; // per-stage parity bits (consumer / producer)

#pragma unroll 1
    for (int c = 0; c < NCH; c++) {
        const int s = cs;
        cs = (cs == 2) ? 0 : cs + 1;
        MBAR_WAIT(sb + SM_MBF + 8 * s, (ph >> s) & 1);
        ph ^= (1u << s);
        const uint32_t Abase = sb + SM_STG + s * STG_SZ;
        const uint32_t Bbase = Abase + A_CH;

#pragma unroll
        for (int ks = 0; ks < 4; ks++) {
            const int kb = ks * 32;
            uint32_t af[2][4];
#pragma unroll
            for (int mi = 0; mi < 2; mi++)
                ldm_x4(af[mi][0], af[mi][1], af[mi][2], af[mi][3],
                       Abase + SWZ((arow + 16 * mi) * 128 + kb + chi));
            uint32_t bf[3][4], bt[2];
#pragma unroll
            for (int ni = 0; ni < 3; ni++)
                ldm_x4(bf[ni][0], bf[ni][1], bf[ni][2], bf[ni][3],
                       Bbase + SWZ((brow + 16 * ni) * 128 + kb + chi));
            ldm_x2(bt[0], bt[1], Bbase + SWZ(btr * 128 + kb + cht));
#pragma unroll
            for (int mi = 0; mi < 2; mi++) {
#pragma unroll
                for (int ni = 0; ni < 3; ni++) {
                    mma16816(acc[mi][2 * ni],     af[mi], bf[ni][0], bf[ni][2]);
                    mma16816(acc[mi][2 * ni + 1], af[mi], bf[ni][1], bf[ni][3]);
                }
                mma16816(acc[mi][6], af[mi], bt[0], bt[1]);
            }
        }
        if (lid == 0) mbar_arrive(sb + SM_MBE + 8 * s);

        if (tid == 0 && c < NCH - 3) {                // refill stage s, chunk c+3
            MBAR_WAIT(sb + SM_MBE + 8 * s, (eph >> s) & 1);
            eph ^= (1u << s);
            uint32_t mb = sb + SM_MBF + 8 * s;
            mbar_expect(mb, STG_SZ);
            bulk_ld(Abase,        Asrc + (size_t)(c + 3) * A_CH, A_CH, mb);
            bulk_ld(Abase + A_CH, Bsrc + (size_t)(c + 3) * B_CH, B_CH, mb);
        }
    }

    // ---- Epilogue: per-row max over i (mask i>=197) -> masked mean over t
    float* rowmax = (float*)(smem + SM_RMAX);          // [64][4]
#pragma unroll
    for (int mi = 0; mi < 2; mi++)
#pragma unroll
        for (int h = 0; h < 2; h++) {
            float m = -3.4e38f;
#pragma unroll
            for (int nj = 0; nj < 7; nj++)
#pragma unroll
                for (int e = 0; e < 2; e++) {
                    int col = 56 * wn + 8 * nj + 2 * (lid & 3) + e;
                    float v = acc[mi][nj][2 * h + e];
                    if (col < I1) m = fmaxf(m, v);
                }
            m = fmaxf(m, __shfl_xor_sync(0xffffffffu, m, 1));
            m = fmaxf(m, __shfl_xor_sync(0xffffffffu, m, 2));
            if ((lid & 3) == 0) {
                int row = 32 * wm + 16 * mi + 8 * h + (lid >> 2);
                rowmax[4 * row + wn] = m;
            }
        }
    __syncthreads();

    if (tid < 64) {
        int row = tid;                                  // x = 2*qh + (row>>5), t = row&31
        float m = fmaxf(fmaxf(rowmax[4 * row], rowmax[4 * row + 1]),
                        fmaxf(rowmax[4 * row + 2], rowmax[4 * row + 3]));
        int xl = row >> 5, t = row & 31;
        int x = 2 * qh + xl;
        int mk = amask[x * T1 + 1 + t] != 0;
        float v = mk ? m * TEMP : 0.f;
        float cnt = mk ? 1.f : 0.f;
#pragma unroll
        for (int o = 16; o > 0; o >>= 1) {
            v   += __shfl_xor_sync(0xffffffffu, v, o);
            cnt += __shfl_xor_sync(0xffffffffu, cnt, o);
        }
        if (t == 0) g_tti[x * NB + y] = v / fmaxf(cnt, 1e-6f);
    }
    __syncthreads();

    // ---- Last CTA computes the loss
    if (tid == 0) {
        __threadfence();
        lastflag = (atomicAdd(&g_cnt, 1) == NCTA - 1);
    }
    __syncthreads();
    if (lastflag) {
        __threadfence();
        float* sl = (float*)(smem + SM_RMAX);          // reuse, [64]
#pragma unroll 1
        for (int rep = 0; rep < 8; rep++) {            // warp wid: rows 8*wid+rep
            int x = 8 * wid + rep;
            const float* row = g_tti + x * NB;
            float e = expf(row[lid]) + expf(row[lid + 32]);
#pragma unroll
            for (int o = 16; o > 0; o >>= 1) e += __shfl_xor_sync(0xffffffffu, e, o);
            if (lid == 0) sl[x] = -logf(expf(row[x]) / e + 1e-20f);
        }
        __syncthreads();
        if (tid < 32) {
            float s = sl[lid] + sl[lid + 32];
#pragma unroll
            for (int o = 16; o > 0; o >>= 1) s += __shfl_xor_sync(0xffffffffu, s, o);
            if (lid == 0) out[0] = s * (1.0f / NB);
        }
    }
}

// ---------------------------------------------------------------------------
extern "C" void kernel_launch(void* const* d_in, const int* in_sizes, int n_in,
                              void* d_out, int out_size) {
    const float* text  = (const float*)d_in[0];
    const float* video = (const float*)d_in[1];
    const int*   mask  = (const int*)d_in[2];

    static int smem_set = 0;
    if (!smem_set) {
        cudaFuncSetAttribute(ksim, cudaFuncAttributeMaxDynamicSharedMemorySize, SM_TOTAL);
        smem_set = 1;
    }

    knorm<<<dim3(NB, 2), 512>>>(text, video);
    ksim<<<dim3(32, NB), 256, SM_TOTAL>>>(mask, (float*)d_out);
}